// round 16
// baseline (speedup 1.0000x reference)
#include <cuda_runtime.h>
#include <cuda_fp16.h>

#define Nn 8192
#define Ff 1024
#define Fk 64
#define Hh 4
#define Cc 256
#define MAXN 128
#define LEAKY 0.2f

// ---- scratch (static device globals: allocation-free) ----
__device__ float    g_feats[(size_t)Nn * Cc];   // 8 MB
__device__ float    g_ss[Hh * Nn];
__device__ float    g_sn[Hh * Nn];
__device__ int      g_nbr[Nn * MAXN];
__device__ int      g_deg[Nn];
__device__ unsigned g_Wh[(size_t)Cc * Ff / 2];  // W transposed to [n=(h,k)][f], fp16 pairs

// ============================================================================
// helpers
// ============================================================================
__device__ __forceinline__ unsigned smem_u32(const void* p) {
    unsigned a;
    asm("{ .reg .u64 t; cvta.to.shared.u64 t, %1; cvt.u32.u64 %0, t; }" : "=r"(a) : "l"(p));
    return a;
}

// fp16 hi/lo split of two floats, packed as half2 words
__device__ __forceinline__ void split2h(float a, float b, unsigned& hi, unsigned& lo) {
    __half ha = __float2half_rn(a), hb = __float2half_rn(b);
    __half la = __float2half_rn(a - __half2float(ha));
    __half lb = __float2half_rn(b - __half2float(hb));
    hi = (unsigned)__half_as_ushort(ha) | ((unsigned)__half_as_ushort(hb) << 16);
    lo = (unsigned)__half_as_ushort(la) | ((unsigned)__half_as_ushort(lb) << 16);
}

// ============================================================================
// convert_w: tiled transpose, both sides coalesced, single fp16 output.
// ============================================================================
__global__ __launch_bounds__(256) void convert_w(const float* __restrict__ W) {
    __shared__ float s[64][65];
    const int h  = blockIdx.x >> 4;
    const int ft = blockIdx.x & 15;
    const int t  = threadIdx.x;
    const float* base = W + (size_t)h * (Ff * Fk) + (size_t)(ft * 64) * Fk;

#pragma unroll
    for (int i = 0; i < 4; i++) {
        int lin = t + i * 256;
        int row = lin >> 4, q = lin & 15;
        float4 v = *(const float4*)(base + row * Fk + q * 4);
        s[row][q * 4 + 0] = v.x;
        s[row][q * 4 + 1] = v.y;
        s[row][q * 4 + 2] = v.z;
        s[row][q * 4 + 3] = v.w;
    }
    __syncthreads();

#pragma unroll
    for (int i = 0; i < 8; i++) {
        int lin = t + i * 256;
        int f2 = lin & 31, k = lin >> 5;
        __half2 hv = __floats2half2_rn(s[2 * f2][k], s[2 * f2 + 1][k]);
        g_Wh[((h * 64 + k) << 9) + ft * 32 + f2] = *(unsigned*)&hv;
    }
}

// ============================================================================
// Tensor-core GEMM (mma.sync fp16 2-term + ldmatrix), fused s epilogue.
// ============================================================================
#define TP   144
#define TSZ  (128 * TP)
#define BUFSZ (3 * TSZ)
#define SMEM_DYN (2 * BUFSZ)

__device__ __forceinline__ void mma16816h(float* d, const unsigned* a, const unsigned* b) {
    asm volatile(
        "mma.sync.aligned.m16n8k16.row.col.f32.f16.f16.f32 "
        "{%0,%1,%2,%3}, {%4,%5,%6,%7}, {%8,%9}, {%0,%1,%2,%3};"
        : "+f"(d[0]), "+f"(d[1]), "+f"(d[2]), "+f"(d[3])
        : "r"(a[0]), "r"(a[1]), "r"(a[2]), "r"(a[3]), "r"(b[0]), "r"(b[1]));
}

#define LDSM4(r0, r1, r2, r3, addr)                                            \
    asm volatile("ldmatrix.sync.aligned.m8n8.x4.shared.b16 {%0,%1,%2,%3}, [%4];" \
        : "=r"(r0), "=r"(r1), "=r"(r2), "=r"(r3) : "r"(addr))

__global__ __launch_bounds__(256) void gemm_kernel(const float* __restrict__ X,
                                                   const float* __restrict__ attn_a) {
    extern __shared__ char dyn[];
    const unsigned sbase = smem_u32(dyn);
    const int t = threadIdx.x;
    const int w = t >> 5, lane = t & 31;
    const int bm = blockIdx.x * 128;
    const int n0 = blockIdx.y * 128;
    const int mrow = (w & 3) * 32;
    const int ncol = (w >> 2) * 64;
    const int r  = lane >> 2;
    const int cb = (lane & 3) * 2;

    const int a_m  = mrow + ((lane >> 3) & 1) * 8 + (lane & 7);
    const int a_k8 = ((lane >> 4) & 1) * 8;
    const int b_n  = ncol + ((lane >> 4) & 1) * 8 + (lane & 7);
    const int b_k8 = ((lane >> 3) & 1) * 8;

    float acc[2][8][4];
#pragma unroll
    for (int a = 0; a < 2; a++)
#pragma unroll
        for (int b = 0; b < 8; b++)
#pragma unroll
            for (int q = 0; q < 4; q++) acc[a][b][q] = 0.f;

    const uint4* WhG = (const uint4*)g_Wh;

    float4 xr[8];
    uint4  whr[4];

    // ---- prologue: load + store chunk 0 ----
#pragma unroll
    for (int i = 0; i < 8; i++) {
        int u = t + i * 256, row = u >> 4, j = u & 15;
        xr[i] = *(const float4*)(X + (size_t)(bm + row) * Ff + j * 4);
    }
#pragma unroll
    for (int i = 0; i < 4; i++) {
        int u = t + i * 256, row = u >> 3, j = u & 7;
        whr[i] = WhG[(size_t)(n0 + row) * 128 + j];
    }
    {
        char* buf = dyn;
#pragma unroll
        for (int i = 0; i < 8; i++) {
            int u = t + i * 256, row = u >> 4, j = u & 15;
            uint2 h, l;
            split2h(xr[i].x, xr[i].y, h.x, l.x);
            split2h(xr[i].z, xr[i].w, h.y, l.y);
            *(uint2*)(buf + row * TP + j * 8)       = h;
            *(uint2*)(buf + TSZ + row * TP + j * 8) = l;
        }
#pragma unroll
        for (int i = 0; i < 4; i++) {
            int u = t + i * 256, row = u >> 3, j = u & 7;
            *(uint4*)(buf + 2 * TSZ + row * TP + j * 16) = whr[i];
        }
    }
    __syncthreads();

#pragma unroll 1
    for (int c = 0; c < 16; c++) {
        if (c < 15) {
#pragma unroll
            for (int i = 0; i < 8; i++) {
                int u = t + i * 256, row = u >> 4, j = u & 15;
                xr[i] = *(const float4*)(X + (size_t)(bm + row) * Ff + (c + 1) * 64 + j * 4);
            }
#pragma unroll
            for (int i = 0; i < 4; i++) {
                int u = t + i * 256, row = u >> 3, j = u & 7;
                whr[i] = WhG[(size_t)(n0 + row) * 128 + (c + 1) * 8 + j];
            }
        }

        {
            const unsigned bufu  = sbase + (c & 1) * BUFSZ;
            const unsigned AhiA  = bufu + a_m * TP + a_k8 * 2;
            const unsigned AloA  = AhiA + TSZ;
            const unsigned BhA   = bufu + 2 * TSZ + b_n * TP + b_k8 * 2;
#pragma unroll
            for (int ks = 0; ks < 4; ks++) {
                const unsigned ko = ks * 32;
                unsigned afh[2][4], afl[2][4];
                unsigned bf[8][2];
#pragma unroll
                for (int mb = 0; mb < 2; mb++) {
                    LDSM4(afh[mb][0], afh[mb][1], afh[mb][2], afh[mb][3],
                          AhiA + mb * (16 * TP) + ko);
                    LDSM4(afl[mb][0], afl[mb][1], afl[mb][2], afl[mb][3],
                          AloA + mb * (16 * TP) + ko);
                }
#pragma unroll
                for (int np = 0; np < 4; np++) {
                    LDSM4(bf[2 * np][0], bf[2 * np][1], bf[2 * np + 1][0], bf[2 * np + 1][1],
                          BhA + np * (16 * TP) + ko);
                }
#pragma unroll
                for (int mb = 0; mb < 2; mb++)
#pragma unroll
                    for (int nb = 0; nb < 8; nb++) {
                        mma16816h(acc[mb][nb], afh[mb], bf[nb]);
                        mma16816h(acc[mb][nb], afl[mb], bf[nb]);
                    }
            }
        }

        if (c < 15) {
            char* buf = dyn + ((c + 1) & 1) * BUFSZ;
#pragma unroll
            for (int i = 0; i < 8; i++) {
                int u = t + i * 256, row = u >> 4, j = u & 15;
                uint2 h, l;
                split2h(xr[i].x, xr[i].y, h.x, l.x);
                split2h(xr[i].z, xr[i].w, h.y, l.y);
                *(uint2*)(buf + row * TP + j * 8)       = h;
                *(uint2*)(buf + TSZ + row * TP + j * 8) = l;
            }
#pragma unroll
            for (int i = 0; i < 4; i++) {
                int u = t + i * 256, row = u >> 3, j = u & 7;
                *(uint4*)(buf + 2 * TSZ + row * TP + j * 16) = whr[i];
            }
            __syncthreads();
        }
    }

    // ---- epilogue 1: write feats ----
#pragma unroll
    for (int mb = 0; mb < 2; mb++) {
        int row0 = bm + mrow + mb * 16 + r;
#pragma unroll
        for (int nb = 0; nb < 8; nb++) {
            int col = n0 + ncol + nb * 8 + cb;
            *(float2*)(g_feats + (size_t)row0 * Cc + col) =
                make_float2(acc[mb][nb][0], acc[mb][nb][1]);
            *(float2*)(g_feats + (size_t)(row0 + 8) * Cc + col) =
                make_float2(acc[mb][nb][2], acc[mb][nb][3]);
        }
    }

    // ---- epilogue 2: fused s_self / s_neigh ----
    {
        int head = (n0 + ncol) >> 6;
        const float* av = attn_a + head * (2 * Fk);
        float ps[4] = {0.f, 0.f, 0.f, 0.f};
        float pn[4] = {0.f, 0.f, 0.f, 0.f};
#pragma unroll
        for (int nb = 0; nb < 8; nb++) {
            int k = nb * 8 + cb;
            float as0 = __ldg(av + k),      as1 = __ldg(av + k + 1);
            float an0 = __ldg(av + 64 + k), an1 = __ldg(av + 64 + k + 1);
#pragma unroll
            for (int mb = 0; mb < 2; mb++) {
                ps[2 * mb + 0] += acc[mb][nb][0] * as0 + acc[mb][nb][1] * as1;
                ps[2 * mb + 1] += acc[mb][nb][2] * as0 + acc[mb][nb][3] * as1;
                pn[2 * mb + 0] += acc[mb][nb][0] * an0 + acc[mb][nb][1] * an1;
                pn[2 * mb + 1] += acc[mb][nb][2] * an0 + acc[mb][nb][3] * an1;
            }
        }
#pragma unroll
        for (int o = 1; o <= 2; o <<= 1) {
#pragma unroll
            for (int i = 0; i < 4; i++) {
                ps[i] += __shfl_xor_sync(0xffffffffu, ps[i], o);
                pn[i] += __shfl_xor_sync(0xffffffffu, pn[i], o);
            }
        }
        if ((lane & 3) == 0) {
#pragma unroll
            for (int i = 0; i < 4; i++) {
                int mb = i >> 1, half = i & 1;
                int row = bm + mrow + mb * 16 + r + half * 8;
                g_ss[head * Nn + row] = ps[i];
                g_sn[head * Nn + row] = pn[i];
            }
        }
    }
}

// ============================================================================
// Adjacency build: one block per row; front-batched 8x LDG.128 for MLP.
// Runs BEFORE gemm so its 256MB stream doesn't evict feats from L2.
// ============================================================================
__global__ __launch_bounds__(256) void adj_kernel(const float* __restrict__ A) {
    int row = blockIdx.x;
    __shared__ int cnt;
    if (threadIdx.x == 0) cnt = 0;
    __syncthreads();
    const float4* ap = (const float4*)(A + (size_t)row * Nn);
    float4 v[8];
#pragma unroll
    for (int i = 0; i < 8; i++) v[i] = ap[threadIdx.x + i * 256];
#pragma unroll
    for (int i = 0; i < 8; i++) {
        int base = (threadIdx.x + i * 256) * 4;
        if (v[i].x != 0.f) { int p = atomicAdd(&cnt, 1); if (p < MAXN) g_nbr[row * MAXN + p] = base; }
        if (v[i].y != 0.f) { int p = atomicAdd(&cnt, 1); if (p < MAXN) g_nbr[row * MAXN + p] = base + 1; }
        if (v[i].z != 0.f) { int p = atomicAdd(&cnt, 1); if (p < MAXN) g_nbr[row * MAXN + p] = base + 2; }
        if (v[i].w != 0.f) { int p = atomicAdd(&cnt, 1); if (p < MAXN) g_nbr[row * MAXN + p] = base + 3; }
    }
    __syncthreads();
    if (threadIdx.x == 0) g_deg[row] = min(cnt, MAXN);
}

// ============================================================================
// Aggregation: block-per-row, warp-per-head, smem weight table,
// gather unrolled x4 for deep L2 MLP.
// ============================================================================
__global__ __launch_bounds__(128) void agg_kernel(const float* __restrict__ bias,
                                                  float* __restrict__ out) {
    int i = blockIdx.x;
    int tid = threadIdx.x;
    int h = tid >> 5, lane = tid & 31;
    __shared__ int   snbr[MAXN];
    __shared__ float sw[Hh][MAXN];

    int d = g_deg[i];
    for (int j = tid; j < d; j += 128) snbr[j] = g_nbr[i * MAXN + j];
    __syncthreads();

    float si = g_ss[h * Nn + i];
    float e[4];
    float mx = -1e30f;
#pragma unroll
    for (int r = 0; r < 4; r++) {
        int j = lane + r * 32;
        if (j < d) {
            float sc = si + g_sn[h * Nn + snbr[j]];
            sc = sc > 0.f ? sc : LEAKY * sc;
            e[r] = sc;
            mx = fmaxf(mx, sc);
        } else {
            e[r] = -1e30f;
        }
    }
#pragma unroll
    for (int o = 16; o; o >>= 1) mx = fmaxf(mx, __shfl_xor_sync(0xffffffffu, mx, o));

    float sum = 0.f;
#pragma unroll
    for (int r = 0; r < 4; r++) {
        int j = lane + r * 32;
        if (j < d) {
            float w = __expf(e[r] - mx);
            sw[h][j] = w;
            sum += w;
        }
    }
#pragma unroll
    for (int o = 16; o; o >>= 1) sum += __shfl_xor_sync(0xffffffffu, sum, o);
    __syncwarp();

    float inv = 1.0f / sum;
    float acc0 = 0.f, acc1 = 0.f;
    int j = 0;
    for (; j + 4 <= d; j += 4) {
        float w0 = sw[h][j],     w1 = sw[h][j + 1];
        float w2 = sw[h][j + 2], w3 = sw[h][j + 3];
        const float* f0 = g_feats + (size_t)snbr[j]     * Cc + h * Fk;
        const float* f1 = g_feats + (size_t)snbr[j + 1] * Cc + h * Fk;
        const float* f2 = g_feats + (size_t)snbr[j + 2] * Cc + h * Fk;
        const float* f3 = g_feats + (size_t)snbr[j + 3] * Cc + h * Fk;
        float a00 = f0[lane], a01 = f0[lane + 32];
        float a10 = f1[lane], a11 = f1[lane + 32];
        float a20 = f2[lane], a21 = f2[lane + 32];
        float a30 = f3[lane], a31 = f3[lane + 32];
        acc0 += w0 * a00 + w1 * a10 + w2 * a20 + w3 * a30;
        acc1 += w0 * a01 + w1 * a11 + w2 * a21 + w3 * a31;
    }
    for (; j < d; j++) {
        float w0 = sw[h][j];
        const float* f0 = g_feats + (size_t)snbr[j] * Cc + h * Fk;
        acc0 += w0 * f0[lane];
        acc1 += w0 * f0[lane + 32];
    }
    float b0 = bias[h * Fk + lane];
    float b1 = bias[h * Fk + lane + 32];
    out[(size_t)i * Cc + h * Fk + lane]      = fmaxf(acc0 * inv + b0, 0.f);
    out[(size_t)i * Cc + h * Fk + lane + 32] = fmaxf(acc1 * inv + b1, 0.f);
}

// ============================================================================
extern "C" void kernel_launch(void* const* d_in, const int* in_sizes, int n_in,
                              void* d_out, int out_size) {
    const float* X      = (const float*)d_in[0];
    const float* A      = (const float*)d_in[1];
    const float* W      = (const float*)d_in[2];
    const float* attn_a = (const float*)d_in[3];
    const float* bias   = (const float*)d_in[4];
    float* out = (float*)d_out;

    static int smem_set = 0;
    if (!smem_set) {
        cudaFuncSetAttribute(gemm_kernel, cudaFuncAttributeMaxDynamicSharedMemorySize, SMEM_DYN);
        smem_set = 1;
    }

    // adj FIRST: its 256MB A-stream would otherwise evict feats from L2
    // between gemm and agg, forcing agg to re-read feats from DRAM.
    convert_w<<<64, 256>>>(W);
    adj_kernel<<<Nn, 256>>>(A);
    gemm_kernel<<<dim3(64, 2), 256, SMEM_DYN>>>(X, attn_a);
    agg_kernel<<<Nn, 128>>>(bias, out);
}

// round 17
// speedup vs baseline: 1.0347x; 1.0347x over previous
#include <cuda_runtime.h>
#include <cuda_fp16.h>

#define Nn 8192
#define Ff 1024
#define Fk 64
#define Hh 4
#define Cc 256
#define MAXN 128
#define LEAKY 0.2f

// ---- scratch (static device globals: allocation-free) ----
__device__ __half2  g_feats2[(size_t)Nn * 128]; // feats as half2 pairs, 4 MB
__device__ float    g_ss[Hh * Nn];
__device__ float    g_sn[Hh * Nn];
__device__ int      g_nbr[Nn * MAXN];
__device__ int      g_deg[Nn];
__device__ unsigned g_Wh[(size_t)Cc * Ff / 2];  // W transposed to [n=(h,k)][f], fp16 pairs

// ============================================================================
// helpers
// ============================================================================
__device__ __forceinline__ unsigned smem_u32(const void* p) {
    unsigned a;
    asm("{ .reg .u64 t; cvta.to.shared.u64 t, %1; cvt.u32.u64 %0, t; }" : "=r"(a) : "l"(p));
    return a;
}

// fp16 hi/lo split of two floats, packed as half2 words
__device__ __forceinline__ void split2h(float a, float b, unsigned& hi, unsigned& lo) {
    __half ha = __float2half_rn(a), hb = __float2half_rn(b);
    __half la = __float2half_rn(a - __half2float(ha));
    __half lb = __float2half_rn(b - __half2float(hb));
    hi = (unsigned)__half_as_ushort(ha) | ((unsigned)__half_as_ushort(hb) << 16);
    lo = (unsigned)__half_as_ushort(la) | ((unsigned)__half_as_ushort(lb) << 16);
}

// ============================================================================
// convert_w: tiled transpose, both sides coalesced, single fp16 output.
// ============================================================================
__global__ __launch_bounds__(256) void convert_w(const float* __restrict__ W) {
    __shared__ float s[64][65];
    const int h  = blockIdx.x >> 4;
    const int ft = blockIdx.x & 15;
    const int t  = threadIdx.x;
    const float* base = W + (size_t)h * (Ff * Fk) + (size_t)(ft * 64) * Fk;

#pragma unroll
    for (int i = 0; i < 4; i++) {
        int lin = t + i * 256;
        int row = lin >> 4, q = lin & 15;
        float4 v = *(const float4*)(base + row * Fk + q * 4);
        s[row][q * 4 + 0] = v.x;
        s[row][q * 4 + 1] = v.y;
        s[row][q * 4 + 2] = v.z;
        s[row][q * 4 + 3] = v.w;
    }
    __syncthreads();

#pragma unroll
    for (int i = 0; i < 8; i++) {
        int lin = t + i * 256;
        int f2 = lin & 31, k = lin >> 5;
        __half2 hv = __floats2half2_rn(s[2 * f2][k], s[2 * f2 + 1][k]);
        g_Wh[((h * 64 + k) << 9) + ft * 32 + f2] = *(unsigned*)&hv;
    }
}

// ============================================================================
// Tensor-core GEMM (mma.sync fp16 2-term + ldmatrix), fused s epilogue.
// ============================================================================
#define TP   144
#define TSZ  (128 * TP)
#define BUFSZ (3 * TSZ)
#define SMEM_DYN (2 * BUFSZ)

__device__ __forceinline__ void mma16816h(float* d, const unsigned* a, const unsigned* b) {
    asm volatile(
        "mma.sync.aligned.m16n8k16.row.col.f32.f16.f16.f32 "
        "{%0,%1,%2,%3}, {%4,%5,%6,%7}, {%8,%9}, {%0,%1,%2,%3};"
        : "+f"(d[0]), "+f"(d[1]), "+f"(d[2]), "+f"(d[3])
        : "r"(a[0]), "r"(a[1]), "r"(a[2]), "r"(a[3]), "r"(b[0]), "r"(b[1]));
}

#define LDSM4(r0, r1, r2, r3, addr)                                            \
    asm volatile("ldmatrix.sync.aligned.m8n8.x4.shared.b16 {%0,%1,%2,%3}, [%4];" \
        : "=r"(r0), "=r"(r1), "=r"(r2), "=r"(r3) : "r"(addr))

__global__ __launch_bounds__(256) void gemm_kernel(const float* __restrict__ X,
                                                   const float* __restrict__ attn_a) {
    extern __shared__ char dyn[];
    const unsigned sbase = smem_u32(dyn);
    const int t = threadIdx.x;
    const int w = t >> 5, lane = t & 31;
    const int bm = blockIdx.x * 128;
    const int n0 = blockIdx.y * 128;
    const int mrow = (w & 3) * 32;
    const int ncol = (w >> 2) * 64;
    const int r  = lane >> 2;
    const int cb = (lane & 3) * 2;

    const int a_m  = mrow + ((lane >> 3) & 1) * 8 + (lane & 7);
    const int a_k8 = ((lane >> 4) & 1) * 8;
    const int b_n  = ncol + ((lane >> 4) & 1) * 8 + (lane & 7);
    const int b_k8 = ((lane >> 3) & 1) * 8;

    float acc[2][8][4];
#pragma unroll
    for (int a = 0; a < 2; a++)
#pragma unroll
        for (int b = 0; b < 8; b++)
#pragma unroll
            for (int q = 0; q < 4; q++) acc[a][b][q] = 0.f;

    const uint4* WhG = (const uint4*)g_Wh;

    float4 xr[8];
    uint4  whr[4];

    // ---- prologue: load + store chunk 0 ----
#pragma unroll
    for (int i = 0; i < 8; i++) {
        int u = t + i * 256, row = u >> 4, j = u & 15;
        xr[i] = *(const float4*)(X + (size_t)(bm + row) * Ff + j * 4);
    }
#pragma unroll
    for (int i = 0; i < 4; i++) {
        int u = t + i * 256, row = u >> 3, j = u & 7;
        whr[i] = WhG[(size_t)(n0 + row) * 128 + j];
    }
    {
        char* buf = dyn;
#pragma unroll
        for (int i = 0; i < 8; i++) {
            int u = t + i * 256, row = u >> 4, j = u & 15;
            uint2 h, l;
            split2h(xr[i].x, xr[i].y, h.x, l.x);
            split2h(xr[i].z, xr[i].w, h.y, l.y);
            *(uint2*)(buf + row * TP + j * 8)       = h;
            *(uint2*)(buf + TSZ + row * TP + j * 8) = l;
        }
#pragma unroll
        for (int i = 0; i < 4; i++) {
            int u = t + i * 256, row = u >> 3, j = u & 7;
            *(uint4*)(buf + 2 * TSZ + row * TP + j * 16) = whr[i];
        }
    }
    __syncthreads();

#pragma unroll 1
    for (int c = 0; c < 16; c++) {
        if (c < 15) {
#pragma unroll
            for (int i = 0; i < 8; i++) {
                int u = t + i * 256, row = u >> 4, j = u & 15;
                xr[i] = *(const float4*)(X + (size_t)(bm + row) * Ff + (c + 1) * 64 + j * 4);
            }
#pragma unroll
            for (int i = 0; i < 4; i++) {
                int u = t + i * 256, row = u >> 3, j = u & 7;
                whr[i] = WhG[(size_t)(n0 + row) * 128 + (c + 1) * 8 + j];
            }
        }

        {
            const unsigned bufu  = sbase + (c & 1) * BUFSZ;
            const unsigned AhiA  = bufu + a_m * TP + a_k8 * 2;
            const unsigned AloA  = AhiA + TSZ;
            const unsigned BhA   = bufu + 2 * TSZ + b_n * TP + b_k8 * 2;
#pragma unroll
            for (int ks = 0; ks < 4; ks++) {
                const unsigned ko = ks * 32;
                unsigned afh[2][4], afl[2][4];
                unsigned bf[8][2];
#pragma unroll
                for (int mb = 0; mb < 2; mb++) {
                    LDSM4(afh[mb][0], afh[mb][1], afh[mb][2], afh[mb][3],
                          AhiA + mb * (16 * TP) + ko);
                    LDSM4(afl[mb][0], afl[mb][1], afl[mb][2], afl[mb][3],
                          AloA + mb * (16 * TP) + ko);
                }
#pragma unroll
                for (int np = 0; np < 4; np++) {
                    LDSM4(bf[2 * np][0], bf[2 * np][1], bf[2 * np + 1][0], bf[2 * np + 1][1],
                          BhA + np * (16 * TP) + ko);
                }
#pragma unroll
                for (int mb = 0; mb < 2; mb++)
#pragma unroll
                    for (int nb = 0; nb < 8; nb++) {
                        mma16816h(acc[mb][nb], afh[mb], bf[nb]);
                        mma16816h(acc[mb][nb], afl[mb], bf[nb]);
                    }
            }
        }

        if (c < 15) {
            char* buf = dyn + ((c + 1) & 1) * BUFSZ;
#pragma unroll
            for (int i = 0; i < 8; i++) {
                int u = t + i * 256, row = u >> 4, j = u & 15;
                uint2 h, l;
                split2h(xr[i].x, xr[i].y, h.x, l.x);
                split2h(xr[i].z, xr[i].w, h.y, l.y);
                *(uint2*)(buf + row * TP + j * 8)       = h;
                *(uint2*)(buf + TSZ + row * TP + j * 8) = l;
            }
#pragma unroll
            for (int i = 0; i < 4; i++) {
                int u = t + i * 256, row = u >> 3, j = u & 7;
                *(uint4*)(buf + 2 * TSZ + row * TP + j * 16) = whr[i];
            }
            __syncthreads();
        }
    }

    // ---- epilogue 1: write feats as half2 (cols cb, cb+1 are adjacent) ----
#pragma unroll
    for (int mb = 0; mb < 2; mb++) {
        int row0 = bm + mrow + mb * 16 + r;
#pragma unroll
        for (int nb = 0; nb < 8; nb++) {
            int col = n0 + ncol + nb * 8 + cb;       // even
            g_feats2[(size_t)row0 * 128 + (col >> 1)] =
                __floats2half2_rn(acc[mb][nb][0], acc[mb][nb][1]);
            g_feats2[(size_t)(row0 + 8) * 128 + (col >> 1)] =
                __floats2half2_rn(acc[mb][nb][2], acc[mb][nb][3]);
        }
    }

    // ---- epilogue 2: fused s_self / s_neigh (fp32, from accumulators) ----
    {
        int head = (n0 + ncol) >> 6;
        const float* av = attn_a + head * (2 * Fk);
        float ps[4] = {0.f, 0.f, 0.f, 0.f};
        float pn[4] = {0.f, 0.f, 0.f, 0.f};
#pragma unroll
        for (int nb = 0; nb < 8; nb++) {
            int k = nb * 8 + cb;
            float as0 = __ldg(av + k),      as1 = __ldg(av + k + 1);
            float an0 = __ldg(av + 64 + k), an1 = __ldg(av + 64 + k + 1);
#pragma unroll
            for (int mb = 0; mb < 2; mb++) {
                ps[2 * mb + 0] += acc[mb][nb][0] * as0 + acc[mb][nb][1] * as1;
                ps[2 * mb + 1] += acc[mb][nb][2] * as0 + acc[mb][nb][3] * as1;
                pn[2 * mb + 0] += acc[mb][nb][0] * an0 + acc[mb][nb][1] * an1;
                pn[2 * mb + 1] += acc[mb][nb][2] * an0 + acc[mb][nb][3] * an1;
            }
        }
#pragma unroll
        for (int o = 1; o <= 2; o <<= 1) {
#pragma unroll
            for (int i = 0; i < 4; i++) {
                ps[i] += __shfl_xor_sync(0xffffffffu, ps[i], o);
                pn[i] += __shfl_xor_sync(0xffffffffu, pn[i], o);
            }
        }
        if ((lane & 3) == 0) {
#pragma unroll
            for (int i = 0; i < 4; i++) {
                int mb = i >> 1, half = i & 1;
                int row = bm + mrow + mb * 16 + r + half * 8;
                g_ss[head * Nn + row] = ps[i];
                g_sn[head * Nn + row] = pn[i];
            }
        }
    }
}

// ============================================================================
// Adjacency build: one block per row; front-batched 8x LDG.128 for MLP.
// ============================================================================
__global__ __launch_bounds__(256) void adj_kernel(const float* __restrict__ A) {
    int row = blockIdx.x;
    __shared__ int cnt;
    if (threadIdx.x == 0) cnt = 0;
    __syncthreads();
    const float4* ap = (const float4*)(A + (size_t)row * Nn);
    float4 v[8];
#pragma unroll
    for (int i = 0; i < 8; i++) v[i] = ap[threadIdx.x + i * 256];
#pragma unroll
    for (int i = 0; i < 8; i++) {
        int base = (threadIdx.x + i * 256) * 4;
        if (v[i].x != 0.f) { int p = atomicAdd(&cnt, 1); if (p < MAXN) g_nbr[row * MAXN + p] = base; }
        if (v[i].y != 0.f) { int p = atomicAdd(&cnt, 1); if (p < MAXN) g_nbr[row * MAXN + p] = base + 1; }
        if (v[i].z != 0.f) { int p = atomicAdd(&cnt, 1); if (p < MAXN) g_nbr[row * MAXN + p] = base + 2; }
        if (v[i].w != 0.f) { int p = atomicAdd(&cnt, 1); if (p < MAXN) g_nbr[row * MAXN + p] = base + 3; }
    }
    __syncthreads();
    if (threadIdx.x == 0) g_deg[row] = min(cnt, MAXN);
}

// ============================================================================
// Aggregation: block-per-row, warp-per-head, smem weight table, x4 unroll.
// Gather reads half2 feats: one 128B wavefront per neighbor per warp.
// Lane handles cols 2*lane, 2*lane+1 of its head.
// ============================================================================
__global__ __launch_bounds__(128) void agg_kernel(const float* __restrict__ bias,
                                                  float* __restrict__ out) {
    int i = blockIdx.x;
    int tid = threadIdx.x;
    int h = tid >> 5, lane = tid & 31;
    __shared__ int   snbr[MAXN];
    __shared__ float sw[Hh][MAXN];

    int d = g_deg[i];
    for (int j = tid; j < d; j += 128) snbr[j] = g_nbr[i * MAXN + j];
    __syncthreads();

    float si = g_ss[h * Nn + i];
    float e[4];
    float mx = -1e30f;
#pragma unroll
    for (int r = 0; r < 4; r++) {
        int j = lane + r * 32;
        if (j < d) {
            float sc = si + g_sn[h * Nn + snbr[j]];
            sc = sc > 0.f ? sc : LEAKY * sc;
            e[r] = sc;
            mx = fmaxf(mx, sc);
        } else {
            e[r] = -1e30f;
        }
    }
#pragma unroll
    for (int o = 16; o; o >>= 1) mx = fmaxf(mx, __shfl_xor_sync(0xffffffffu, mx, o));

    float sum = 0.f;
#pragma unroll
    for (int r = 0; r < 4; r++) {
        int j = lane + r * 32;
        if (j < d) {
            float w = __expf(e[r] - mx);
            sw[h][j] = w;
            sum += w;
        }
    }
#pragma unroll
    for (int o = 16; o; o >>= 1) sum += __shfl_xor_sync(0xffffffffu, sum, o);
    __syncwarp();

    float inv = 1.0f / sum;
    float acc0 = 0.f, acc1 = 0.f;
    const size_t hoff = (size_t)h * 32 + lane;
    int j = 0;
    for (; j + 4 <= d; j += 4) {
        float w0 = sw[h][j],     w1 = sw[h][j + 1];
        float w2 = sw[h][j + 2], w3 = sw[h][j + 3];
        float2 f0 = __half22float2(g_feats2[(size_t)snbr[j]     * 128 + hoff]);
        float2 f1 = __half22float2(g_feats2[(size_t)snbr[j + 1] * 128 + hoff]);
        float2 f2 = __half22float2(g_feats2[(size_t)snbr[j + 2] * 128 + hoff]);
        float2 f3 = __half22float2(g_feats2[(size_t)snbr[j + 3] * 128 + hoff]);
        acc0 += w0 * f0.x + w1 * f1.x + w2 * f2.x + w3 * f3.x;
        acc1 += w0 * f0.y + w1 * f1.y + w2 * f2.y + w3 * f3.y;
    }
    for (; j < d; j++) {
        float w0 = sw[h][j];
        float2 f0 = __half22float2(g_feats2[(size_t)snbr[j] * 128 + hoff]);
        acc0 += w0 * f0.x;
        acc1 += w0 * f0.y;
    }
    const int col = h * Fk + 2 * lane;
    float2 ov;
    ov.x = fmaxf(acc0 * inv + bias[col], 0.f);
    ov.y = fmaxf(acc1 * inv + bias[col + 1], 0.f);
    *(float2*)(out + (size_t)i * Cc + col) = ov;
}

// ============================================================================
extern "C" void kernel_launch(void* const* d_in, const int* in_sizes, int n_in,
                              void* d_out, int out_size) {
    const float* X      = (const float*)d_in[0];
    const float* A      = (const float*)d_in[1];
    const float* W      = (const float*)d_in[2];
    const float* attn_a = (const float*)d_in[3];
    const float* bias   = (const float*)d_in[4];
    float* out = (float*)d_out;

    static int smem_set = 0;
    if (!smem_set) {
        cudaFuncSetAttribute(gemm_kernel, cudaFuncAttributeMaxDynamicSharedMemorySize, SMEM_DYN);
        smem_set = 1;
    }

    convert_w<<<64, 256>>>(W);
    adj_kernel<<<Nn, 256>>>(A);
    gemm_kernel<<<dim3(64, 2), 256, SMEM_DYN>>>(X, attn_a);
    agg_kernel<<<Nn, 128>>>(bias, out);
}